// round 12
// baseline (speedup 1.0000x reference)
#include <cuda_runtime.h>
#include <cuda_bf16.h>
#include <cstdint>

// Problem: B=32, T=32, L=196, S=512, D=512
// Math reduction: softmax is shift-invariant => attention independent of h,t.
//   attn[b,:]  = softmax_l( x_static[b] @ (W1@V) )
//   ctx[b,:]   = attn[b,:] @ x_static[b]
//   out[b,t,:] = concat(x[b,t,:], ctx[b,:]) @ W3 + b3   (K=1024 TF32 MMA GEMM)
//
// 4 launches: prep_fused -> scores -> ctx_fused -> gemm_tc (split-K=2, counter
// reduction). Launch-count and GEMM latency are the binding constraints.

#define D_ 512
#define S_ 512
#define L_ 196
#define B_ 32
#define T_ 32
#define KTOT 1024
#define M_ 1024
#define LCH 7
#define LPC 28
#define NTILE 16   // K-tiles per ksplit (16 * 32 = 512)

__device__ float g_w1v[S_];
__device__ float g_scores[B_ * L_];
__device__ float g_ctxpart[LCH][B_][S_];
__device__ unsigned int g_ctx_cnt[B_];
__device__ unsigned int g_gemm_cnt[16 * 8];
__device__ float g_part[2][M_][D_];      // split-K fp32 partials
__device__ uint32_t g_Ax32[M_ * D_];     // tf32 x
__device__ uint32_t g_ctx32[B_ * S_];    // tf32 ctx (compact)
__device__ uint32_t g_W332[KTOT * D_];   // tf32 W3

__device__ __forceinline__ uint32_t f2tf32(float f) {
    uint32_t u;
    asm("cvt.rna.tf32.f32 %0, %1;" : "=r"(u) : "f"(f));
    return u;
}
__device__ __forceinline__ void cp_async16(uint32_t smem_addr, const void* gptr) {
    asm volatile("cp.async.cg.shared.global [%0], [%1], 16;\n" ::"r"(smem_addr),
                 "l"(gptr));
}
__device__ __forceinline__ void cp_commit() {
    asm volatile("cp.async.commit_group;\n");
}
template <int N>
__device__ __forceinline__ void cp_wait() {
    asm volatile("cp.async.wait_group %0;\n" ::"n"(N));
}

// ---------------------------------------------------------------------------
// Kernel 1 (fused prep): x->tf32, W3->tf32, w1v = W1@V, counter resets.
// ---------------------------------------------------------------------------
__global__ __launch_bounds__(256) void prep_fused(const float* __restrict__ x,
                                                  const float* __restrict__ W3,
                                                  const float* __restrict__ W1,
                                                  const float* __restrict__ V) {
    int gtid = blockIdx.x * 256 + threadIdx.x;  // 65536 threads

    if (blockIdx.x == 0 && threadIdx.x < B_) g_ctx_cnt[threadIdx.x] = 0u;
    if (blockIdx.x == 1 && threadIdx.x < 128) g_gemm_cnt[threadIdx.x] = 0u;

#pragma unroll
    for (int it = 0; it < 2; it++) {
        int j = (gtid + it * 65536) * 4;
        float4 v = *(const float4*)(x + j);
        uint4 u;
        u.x = f2tf32(v.x);
        u.y = f2tf32(v.y);
        u.z = f2tf32(v.z);
        u.w = f2tf32(v.w);
        *(uint4*)(g_Ax32 + j) = u;
    }
#pragma unroll
    for (int it = 0; it < 2; it++) {
        int j = (gtid + it * 65536) * 4;
        float4 v = *(const float4*)(W3 + j);
        uint4 u;
        u.x = f2tf32(v.x);
        u.y = f2tf32(v.y);
        u.z = f2tf32(v.z);
        u.w = f2tf32(v.w);
        *(uint4*)(g_W332 + j) = u;
    }

    int gwarp = gtid >> 5;
    int lane = threadIdx.x & 31;
    if (gwarp < S_) {
        const float4* row = (const float4*)(W1 + (size_t)gwarp * D_);
        const float4* v4 = (const float4*)V;
        float acc = 0.0f;
#pragma unroll
        for (int i = 0; i < 4; i++) {
            int idx = lane + i * 32;
            float4 a = row[idx];
            float4 b = v4[idx];
            acc += a.x * b.x + a.y * b.y + a.z * b.z + a.w * b.w;
        }
#pragma unroll
        for (int o = 16; o; o >>= 1) acc += __shfl_xor_sync(0xffffffffu, acc, o);
        if (lane == 0) g_w1v[gwarp] = acc;
    }
}

// ---------------------------------------------------------------------------
// Kernel 2: scores[b,l] = dot(x_static[b,l,:], w1v). grid (7, 32), warp/row.
// ---------------------------------------------------------------------------
__global__ __launch_bounds__(256) void scores_kernel(const float* __restrict__ xs) {
    int b = blockIdx.y;
    int l0 = blockIdx.x * LPC;
    __shared__ float sw1v[S_];
    int tid = threadIdx.x;
    if (tid < S_ / 4) ((float4*)sw1v)[tid] = ((const float4*)g_w1v)[tid];
    __syncthreads();

    int warp = tid >> 5, lane = tid & 31;
    const float* X = xs + (size_t)b * L_ * S_;
    for (int r = warp; r < LPC; r += 8) {
        int l = l0 + r;
        const float4* row = (const float4*)(X + (size_t)l * S_);
        const float4* w4 = (const float4*)sw1v;
        float acc = 0.0f;
#pragma unroll
        for (int i = 0; i < 4; i++) {
            int idx = lane + i * 32;
            float4 a = row[idx];
            float4 w = w4[idx];
            acc += a.x * w.x + a.y * w.y + a.z * w.z + a.w * w.w;
        }
#pragma unroll
        for (int o = 16; o; o >>= 1) acc += __shfl_xor_sync(0xffffffffu, acc, o);
        if (lane == 0) g_scores[b * L_ + l] = acc;
    }
}

// ---------------------------------------------------------------------------
// Kernel 3 (fused): softmax recompute + ctx partial + last-block reduce.
// grid (7 l-chunks, 32 b), block 128.
// ---------------------------------------------------------------------------
__global__ __launch_bounds__(128) void ctx_fused(const float* __restrict__ xs) {
    int b = blockIdx.y;
    int lc = blockIdx.x;
    int l0 = lc * LPC;
    int tid = threadIdx.x;
    int warp = tid >> 5, lane = tid & 31;

    __shared__ float ssc[256];
    __shared__ float red[4];
    __shared__ float s_max, s_sum;
    __shared__ unsigned int s_last;
    __shared__ float sattn[LPC];

    float v0 = g_scores[b * L_ + tid];
    float v1 = (tid + 128 < L_) ? g_scores[b * L_ + tid + 128] : -1e30f;
    ssc[tid] = v0;
    ssc[tid + 128] = v1;

    float m = fmaxf(v0, v1);
#pragma unroll
    for (int o = 16; o; o >>= 1) m = fmaxf(m, __shfl_xor_sync(0xffffffffu, m, o));
    if (lane == 0) red[warp] = m;
    __syncthreads();
    if (tid == 0) s_max = fmaxf(fmaxf(red[0], red[1]), fmaxf(red[2], red[3]));
    __syncthreads();
    float mx = s_max;

    float e0 = __expf(v0 - mx);
    float e1 = (tid + 128 < L_) ? __expf(v1 - mx) : 0.0f;
    float ps = e0 + e1;
#pragma unroll
    for (int o = 16; o; o >>= 1) ps += __shfl_xor_sync(0xffffffffu, ps, o);
    if (lane == 0) red[warp] = ps;
    __syncthreads();
    if (tid == 0) s_sum = red[0] + red[1] + red[2] + red[3];
    __syncthreads();
    float inv = 1.0f / s_sum;

    if (tid < LPC) sattn[tid] = __expf(ssc[l0 + tid] - mx) * inv;
    __syncthreads();

    const float4* Xp = (const float4*)(xs + (size_t)b * L_ * S_ + (size_t)l0 * S_) + tid;
    float4 acc = {0.0f, 0.0f, 0.0f, 0.0f};
#pragma unroll 4
    for (int l = 0; l < LPC; l++) {
        float w = sattn[l];
        float4 v = Xp[l * (S_ / 4)];
        acc.x += w * v.x;
        acc.y += w * v.y;
        acc.z += w * v.z;
        acc.w += w * v.w;
    }
    *(float4*)&g_ctxpart[lc][b][tid * 4] = acc;

    __threadfence();
    __syncthreads();
    if (tid == 0) s_last = atomicAdd(&g_ctx_cnt[b], 1u);
    __syncthreads();
    if (s_last == LCH - 1) {
        __threadfence();
        float4 t = {0.0f, 0.0f, 0.0f, 0.0f};
#pragma unroll
        for (int k = 0; k < LCH; k++) {
            float4 p = *(const float4*)&g_ctxpart[k][b][tid * 4];
            t.x += p.x;
            t.y += p.y;
            t.z += p.z;
            t.w += p.w;
        }
        uint4 u;
        u.x = f2tf32(t.x);
        u.y = f2tf32(t.y);
        u.z = f2tf32(t.z);
        u.w = f2tf32(t.w);
        *(uint4*)(g_ctx32 + b * S_ + tid * 4) = u;
    }
}

// ---------------------------------------------------------------------------
// Kernel 4: split-K TF32 MMA GEMM. grid (8 n, 16 m, 2 ksplit), 128 threads.
// ksplit 0: A = g_Ax32 (k 0..511); ksplit 1: A = g_ctx32 broadcast (k 512..1023).
// Last-arriving CTA per tile adds the other half's partial + bias -> out.
// ---------------------------------------------------------------------------
#define GBM 64
#define GBN 64
#define GBK 32

__global__ __launch_bounds__(128) void gemm_tc(const float* __restrict__ b3,
                                               float* __restrict__ out) {
    __shared__ uint32_t As[2][GBM][36];
    __shared__ uint32_t Bs[2][GBK][72];
    __shared__ unsigned int s_flag;

    int tid = threadIdx.x;
    int w = tid >> 5, lane = tid & 31;
    int m0 = blockIdx.y * GBM, n0 = blockIdx.x * GBN;
    int ks = blockIdx.z;
    int kbase = ks * 512;
    int m_warp = (w & 1) * 32;
    int n_warp = (w >> 1) * 32;
    int r = lane >> 2;
    int c = lane & 3;

    float d[2][4][4];
#pragma unroll
    for (int f = 0; f < 2; f++)
#pragma unroll
        for (int g = 0; g < 4; g++)
#pragma unroll
            for (int i = 0; i < 4; i++) d[f][g][i] = 0.0f;

    int arow[4], ac4[4], bk[4], bn4[4];
#pragma unroll
    for (int it = 0; it < 4; it++) {
        int slot = tid + it * 128;
        arow[it] = slot >> 3;
        ac4[it] = slot & 7;
        bk[it] = slot >> 4;
        bn4[it] = slot & 15;
    }

    // per-ksplit A row base pointers (resolved once)
    const uint32_t* abase[4];
#pragma unroll
    for (int it = 0; it < 4; it++) {
        abase[it] = (ks == 0)
                        ? g_Ax32 + (size_t)(m0 + arow[it]) * D_
                        : g_ctx32 + (size_t)((m0 + arow[it]) >> 5) * S_;
    }

    auto issue_tile = [&](int kk, int buf) {
#pragma unroll
        for (int it = 0; it < 4; it++) {
            uint32_t dst =
                (uint32_t)__cvta_generic_to_shared(&As[buf][arow[it]][ac4[it] * 4]);
            cp_async16(dst, abase[it] + kk + ac4[it] * 4);
        }
#pragma unroll
        for (int it = 0; it < 4; it++) {
            uint32_t dst =
                (uint32_t)__cvta_generic_to_shared(&Bs[buf][bk[it]][bn4[it] * 4]);
            cp_async16(dst, g_W332 + (size_t)(kbase + kk + bk[it]) * D_ + n0 + bn4[it] * 4);
        }
        cp_commit();
    };

    issue_tile(0, 0);

    for (int t = 0; t < NTILE; t++) {
        int buf = t & 1;
        if (t + 1 < NTILE) {
            issue_tile((t + 1) * GBK, buf ^ 1);
            cp_wait<1>();
        } else {
            cp_wait<0>();
        }
        __syncthreads();

#pragma unroll
        for (int kk8 = 0; kk8 < 4; kk8++) {
            int kb = kk8 * 8;
            uint32_t a[2][4];
#pragma unroll
            for (int f = 0; f < 2; f++) {
                int mrow = m_warp + f * 16 + r;
                a[f][0] = As[buf][mrow][kb + c];
                a[f][1] = As[buf][mrow + 8][kb + c];
                a[f][2] = As[buf][mrow][kb + c + 4];
                a[f][3] = As[buf][mrow + 8][kb + c + 4];
            }
#pragma unroll
            for (int g = 0; g < 4; g++) {
                int ncol = n_warp + g * 8 + r;
                uint32_t b0 = Bs[buf][kb + c][ncol];
                uint32_t b1 = Bs[buf][kb + c + 4][ncol];
#pragma unroll
                for (int f = 0; f < 2; f++) {
                    asm volatile(
                        "mma.sync.aligned.m16n8k8.row.col.f32.tf32.tf32.f32 "
                        "{%0,%1,%2,%3}, {%4,%5,%6,%7}, {%8,%9}, {%0,%1,%2,%3};\n"
                        : "+f"(d[f][g][0]), "+f"(d[f][g][1]), "+f"(d[f][g][2]),
                          "+f"(d[f][g][3])
                        : "r"(a[f][0]), "r"(a[f][1]), "r"(a[f][2]), "r"(a[f][3]),
                          "r"(b0), "r"(b1));
                }
            }
        }
        __syncthreads();
    }

    // write my partial (no bias)
    int c2 = c * 2;
#pragma unroll
    for (int g = 0; g < 4; g++) {
        int n = n0 + n_warp + g * 8 + c2;
#pragma unroll
        for (int f = 0; f < 2; f++) {
            int m = m0 + m_warp + f * 16 + r;
            float2 p0 = {d[f][g][0], d[f][g][1]};
            float2 p1 = {d[f][g][2], d[f][g][3]};
            *(float2*)&g_part[ks][m][n] = p0;
            *(float2*)&g_part[ks][m + 8][n] = p1;
        }
    }
    __threadfence();
    __syncthreads();
    if (tid == 0) s_flag = atomicAdd(&g_gemm_cnt[blockIdx.y * 8 + blockIdx.x], 1u);
    __syncthreads();

    if (s_flag == 1) {
        __threadfence();
        int other = 1 - ks;
#pragma unroll
        for (int g = 0; g < 4; g++) {
            int n = n0 + n_warp + g * 8 + c2;
            float2 bias = *(const float2*)(b3 + n);
#pragma unroll
            for (int f = 0; f < 2; f++) {
                int m = m0 + m_warp + f * 16 + r;
                float2 q0 = *(const float2*)&g_part[other][m][n];
                float2 q1 = *(const float2*)&g_part[other][m + 8][n];
                float2 o0, o1;
                o0.x = d[f][g][0] + q0.x + bias.x;
                o0.y = d[f][g][1] + q0.y + bias.y;
                o1.x = d[f][g][2] + q1.x + bias.x;
                o1.y = d[f][g][3] + q1.y + bias.y;
                *(float2*)(out + (size_t)m * D_ + n) = o0;
                *(float2*)(out + (size_t)(m + 8) * D_ + n) = o1;
            }
        }
    }
}

extern "C" void kernel_launch(void* const* d_in, const int* in_sizes, int n_in,
                              void* d_out, int out_size) {
    const float* x  = (const float*)d_in[0];   // [32,32,512]
    const float* xs = (const float*)d_in[1];   // [32,196,512]
    const float* W1 = (const float*)d_in[3];   // [512,512]
    const float* W3 = (const float*)d_in[5];   // [1024,512]
    const float* b3 = (const float*)d_in[7];   // [512]
    const float* V  = (const float*)d_in[8];   // [512,1]
    float* out = (float*)d_out;                // [32,32,512]

    prep_fused<<<256, 256>>>(x, W3, W1, V);
    scores_kernel<<<dim3(LCH, B_), 256>>>(xs);
    ctx_fused<<<dim3(LCH, B_), 128>>>(xs);
    gemm_tc<<<dim3(D_ / GBN, M_ / GBM, 2), 128>>>(b3, out);
}